// round 3
// baseline (speedup 1.0000x reference)
#include <cuda_runtime.h>

#define N_NODES  50000
#define N_EDGES  800000
#define N_GRAPHS 64
#define NEG      0.2f

// ---------------- device scratch (no allocations allowed) ----------------
__device__ float  g_e[N_EDGES];
__device__ float  g_s[N_NODES];
__device__ float  g_d[N_NODES];
__device__ float  g_m[N_NODES];
__device__ float4 g_agg1[N_NODES];                    // (sum, ax, ay, az)
__device__ __align__(16) float g_x1[N_NODES * 8];     // layer-1 output features
__device__ __align__(16) float g_agg2[N_NODES * 12];  // [sum, a0..a7, pad3] stride 48B
__device__ float  g_wa[6 + 16];   // wa_src1[3], wa_dst1[3], wa_src2[8], wa_dst2[8]

__device__ __forceinline__ float lrelu(float v) { return v > 0.f ? v : NEG * v; }

__device__ __forceinline__ void atomicMaxF(float* addr, float v) {
    if (v >= 0.f) atomicMax((int*)addr, __float_as_int(v));
    else          atomicMin((unsigned int*)addr, __float_as_uint(v));
}

// ---------------- prep: fold W@a vectors, zero output (1 block) ----------------
__global__ void k_prep(const float* __restrict__ W1, const float* __restrict__ as1,
                       const float* __restrict__ ad1,
                       const float* __restrict__ W2, const float* __restrict__ as2,
                       const float* __restrict__ ad2,
                       float* __restrict__ out) {
    int t = threadIdx.x;
    if (t < 3) {
        float a = 0.f, b = 0.f;
        #pragma unroll
        for (int j = 0; j < 8; j++) {
            float w = W1[t * 8 + j];
            a += w * as1[j];
            b += w * ad1[j];
        }
        g_wa[t] = a;
        g_wa[3 + t] = b;
    } else if (t >= 32 && t < 40) {
        int k = t - 32;
        float a = 0.f, b = 0.f;
        for (int f = 0; f < 256; f++) {
            float w = W2[k * 256 + f];
            a += w * as2[f];
            b += w * ad2[f];
        }
        g_wa[6 + k]  = a;
        g_wa[14 + k] = b;
    } else if (t >= 64 && t < 64 + N_GRAPHS) {
        out[t - 64] = 0.f;
    }
}

// ---------------- layer1 node init: s,d scalars, self-loop seeds max ----------
__global__ void k_node1_init(const float* __restrict__ x) {
    int v = blockIdx.x * blockDim.x + threadIdx.x;
    if (v >= N_NODES) return;
    float x0 = x[v * 3 + 0], x1 = x[v * 3 + 1], x2 = x[v * 3 + 2];
    float s = x0 * g_wa[0] + x1 * g_wa[1] + x2 * g_wa[2];
    float d = x0 * g_wa[3] + x1 * g_wa[4] + x2 * g_wa[5];
    g_s[v] = s;
    g_d[v] = d;
    g_m[v] = lrelu(s + d);          // self-loop logit seeds the segment max
    g_agg1[v] = make_float4(0.f, 0.f, 0.f, 0.f);
}

// ---------------- edge pass A (both layers): logits + segment max -------------
__global__ void k_edgeA(const int* __restrict__ ei) {
    int i = blockIdx.x * blockDim.x + threadIdx.x;
    if (i >= N_EDGES) return;
    int s = ei[i], d = ei[N_EDGES + i];
    float e = lrelu(g_s[s] + g_d[d]);
    g_e[i] = e;
    atomicMaxF(&g_m[d], e);
}

// ---------------- edge pass B layer1: exp + scatter (sum, w*x) -----------------
__global__ void k_edgeB1(const int* __restrict__ ei, const float* __restrict__ x) {
    int i = blockIdx.x * blockDim.x + threadIdx.x;
    if (i >= N_EDGES) return;
    int s = ei[i], d = ei[N_EDGES + i];
    float w = __expf(g_e[i] - g_m[d]);
    float* ag = (float*)&g_agg1[d];
    atomicAdd(ag + 0, w);
    atomicAdd(ag + 1, w * x[s * 3 + 0]);
    atomicAdd(ag + 2, w * x[s * 3 + 1]);
    atomicAdd(ag + 3, w * x[s * 3 + 2]);
}

// ------- layer1 finalize: add self-loop, normalize, project W1, prep layer2 ----
__global__ void k_node1_fin(const float* __restrict__ x,
                            const float* __restrict__ W1,
                            const float* __restrict__ b1) {
    int v = blockIdx.x * blockDim.x + threadIdx.x;
    if (v >= N_NODES) return;
    float s = g_s[v], d = g_d[v];
    float w = __expf(lrelu(s + d) - g_m[v]);      // self-loop weight
    float4 a = g_agg1[v];
    float x0 = x[v * 3 + 0], x1 = x[v * 3 + 1], x2 = x[v * 3 + 2];
    float inv = 1.f / (a.x + w);
    float t0 = (a.y + w * x0) * inv;
    float t1 = (a.z + w * x1) * inv;
    float t2 = (a.w + w * x2) * inv;

    float s2 = 0.f, d2 = 0.f;
    #pragma unroll
    for (int f = 0; f < 8; f++) {
        float y = t0 * W1[f] + t1 * W1[8 + f] + t2 * W1[16 + f] + b1[f];
        y = y > 0.f ? y : 0.f;                    // relu
        g_x1[v * 8 + f] = y;
        s2 += y * g_wa[6 + f];
        d2 += y * g_wa[14 + f];
    }
    g_s[v] = s2;
    g_d[v] = d2;
    g_m[v] = lrelu(s2 + d2);                      // self-loop seeds layer-2 max
    #pragma unroll
    for (int k = 0; k < 9; k++) g_agg2[v * 12 + k] = 0.f;
}

// ---------------- edge pass B layer2: exp + scatter (sum, w*h[8]) --------------
__global__ void k_edgeB2(const int* __restrict__ ei) {
    int i = blockIdx.x * blockDim.x + threadIdx.x;
    if (i >= N_EDGES) return;
    int s = ei[i], d = ei[N_EDGES + i];
    float w = __expf(g_e[i] - g_m[d]);
    const float4* hp = (const float4*)(g_x1 + s * 8);
    float4 h0 = hp[0], h1 = hp[1];
    float* ag = g_agg2 + d * 12;
    atomicAdd(ag + 0, w);
    atomicAdd(ag + 1, w * h0.x);
    atomicAdd(ag + 2, w * h0.y);
    atomicAdd(ag + 3, w * h0.z);
    atomicAdd(ag + 4, w * h0.w);
    atomicAdd(ag + 5, w * h1.x);
    atomicAdd(ag + 6, w * h1.y);
    atomicAdd(ag + 7, w * h1.z);
    atomicAdd(ag + 8, w * h1.w);
}

// -------- layer2 finalize + W2 projection + ReLU + FC + graph pooling ----------
__global__ void k_node2_fin(const int* __restrict__ batch,
                            const float* __restrict__ W2,
                            const float* __restrict__ b2,
                            const float* __restrict__ fcw,
                            const float* __restrict__ fcb,
                            float* __restrict__ out) {
    __shared__ float4 sW2[512];   // [k][f/4] : k*64 + f4
    __shared__ float4 sb2[64];
    __shared__ float4 sfw[64];
    __shared__ float  sg[N_GRAPHS];

    int tid = threadIdx.x;
    for (int j = tid; j < 512; j += blockDim.x) {
        sW2[j] = ((const float4*)W2)[j];   // identical layout repack
    }
    for (int j = tid; j < 64; j += blockDim.x) {
        sb2[j] = ((const float4*)b2)[j];
        sfw[j] = ((const float4*)fcw)[j];
    }
    if (tid < N_GRAPHS) sg[tid] = 0.f;
    __syncthreads();

    int v = blockIdx.x * blockDim.x + tid;
    if (v < N_NODES) {
        float s = g_s[v], d = g_d[v];
        float w = __expf(lrelu(s + d) - g_m[v]);
        const float* ag = g_agg2 + v * 12;
        const float4* hp = (const float4*)(g_x1 + v * 8);
        float4 h0 = hp[0], h1 = hp[1];
        float inv = 1.f / (ag[0] + w);
        float t[8];
        t[0] = (ag[1] + w * h0.x) * inv;
        t[1] = (ag[2] + w * h0.y) * inv;
        t[2] = (ag[3] + w * h0.z) * inv;
        t[3] = (ag[4] + w * h0.w) * inv;
        t[4] = (ag[5] + w * h1.x) * inv;
        t[5] = (ag[6] + w * h1.y) * inv;
        t[6] = (ag[7] + w * h1.z) * inv;
        t[7] = (ag[8] + w * h1.w) * inv;

        float acc = 0.f;
        #pragma unroll 4
        for (int f4 = 0; f4 < 64; f4++) {
            float4 y = sb2[f4];
            #pragma unroll
            for (int k = 0; k < 8; k++) {
                float4 wv = sW2[k * 64 + f4];
                y.x += t[k] * wv.x;
                y.y += t[k] * wv.y;
                y.z += t[k] * wv.z;
                y.w += t[k] * wv.w;
            }
            y.x = y.x > 0.f ? y.x : 0.f;
            y.y = y.y > 0.f ? y.y : 0.f;
            y.z = y.z > 0.f ? y.z : 0.f;
            y.w = y.w > 0.f ? y.w : 0.f;
            float4 fw = sfw[f4];
            acc += y.x * fw.x + y.y * fw.y + y.z * fw.z + y.w * fw.w;
        }
        acc += fcb[0];
        atomicAdd(&sg[batch[v]], acc);
    }
    __syncthreads();
    if (tid < N_GRAPHS) atomicAdd(&out[tid], sg[tid]);
}

// --------------------------------- launch --------------------------------------
extern "C" void kernel_launch(void* const* d_in, const int* in_sizes, int n_in,
                              void* d_out, int out_size) {
    const float* x     = (const float*)d_in[0];
    const int*   ei    = (const int*)d_in[1];     // int64 delivered as int32
    // d_in[2] = edge_attr (unused by GATConv with edge_dim=None)
    const int*   batch = (const int*)d_in[3];     // int64 delivered as int32
    const float* W1    = (const float*)d_in[4];
    const float* as1   = (const float*)d_in[5];
    const float* ad1   = (const float*)d_in[6];
    const float* b1    = (const float*)d_in[7];
    const float* W2    = (const float*)d_in[8];
    const float* as2   = (const float*)d_in[9];
    const float* ad2   = (const float*)d_in[10];
    const float* b2    = (const float*)d_in[11];
    const float* fcw   = (const float*)d_in[12];
    const float* fcb   = (const float*)d_in[13];
    float*       out   = (float*)d_out;

    const int EB = (N_EDGES + 255) / 256;   // 3125
    const int NB = (N_NODES + 255) / 256;   // 196

    k_prep<<<1, 128>>>(W1, as1, ad1, W2, as2, ad2, out);
    k_node1_init<<<NB, 256>>>(x);
    k_edgeA<<<EB, 256>>>(ei);
    k_edgeB1<<<EB, 256>>>(ei, x);
    k_node1_fin<<<NB, 256>>>(x, W1, b1);
    k_edgeA<<<EB, 256>>>(ei);
    k_edgeB2<<<EB, 256>>>(ei);
    k_node2_fin<<<NB, 256>>>(batch, W2, b2, fcw, fcb, out);
}

// round 4
// speedup vs baseline: 2.0207x; 2.0207x over previous
#include <cuda_runtime.h>

#define N_NODES  50000
#define N_EDGES  800000
#define N_GRAPHS 64
#define NEG      0.2f

// ---------------- device scratch (no allocations allowed) ----------------
__device__ float4 g_x4[N_NODES];                      // (s1, x0, x1, x2)
__device__ float  g_d1[N_NODES];                      // d1 scalar per node
__device__ float4 g_agg1[N_NODES];                    // (sum, ax, ay, az)
__device__ __align__(16) float g_h[N_NODES * 12];     // [s2, h0..h7, d2, pad2] 48B/node
__device__ __align__(16) float g_agg2[N_NODES * 12];  // [sum,-,-,-, a0..a3, a4..a7]
__device__ float  g_wa[6 + 16];   // wa_src1[3], wa_dst1[3], wa_src2[8], wa_dst2[8]

__device__ __forceinline__ float lrelu(float v) { return v > 0.f ? v : NEG * v; }

__device__ __forceinline__ void red_add_v4(float* addr, float a, float b, float c, float d) {
    asm volatile("red.global.add.v4.f32 [%0], {%1,%2,%3,%4};"
                 :: "l"(addr), "f"(a), "f"(b), "f"(c), "f"(d) : "memory");
}

// ---------------- prep: fold W@a vectors, zero output (1 block) ----------------
__global__ void k_prep(const float* __restrict__ W1, const float* __restrict__ as1,
                       const float* __restrict__ ad1,
                       const float* __restrict__ W2, const float* __restrict__ as2,
                       const float* __restrict__ ad2,
                       float* __restrict__ out) {
    int t = threadIdx.x;
    if (t < 3) {
        float a = 0.f, b = 0.f;
        #pragma unroll
        for (int j = 0; j < 8; j++) {
            float w = W1[t * 8 + j];
            a += w * as1[j];
            b += w * ad1[j];
        }
        g_wa[t] = a;
        g_wa[3 + t] = b;
    }
    if (t < N_GRAPHS) out[t] = 0.f;
    // wa2: 8 warps, one per k-row of W2^T; each lane sums 8 contiguous f's
    if (t >= 64 && t < 64 + 256) {
        int k = (t - 64) >> 5;
        int lane = t & 31;
        float a = 0.f, b = 0.f;
        #pragma unroll
        for (int j = 0; j < 8; j++) {
            int f = lane * 8 + j;
            float w = W2[k * 256 + f];
            a += w * as2[f];
            b += w * ad2[f];
        }
        #pragma unroll
        for (int o = 16; o > 0; o >>= 1) {
            a += __shfl_down_sync(0xffffffffu, a, o);
            b += __shfl_down_sync(0xffffffffu, b, o);
        }
        if (lane == 0) {
            g_wa[6 + k]  = a;
            g_wa[14 + k] = b;
        }
    }
}

// ---------------- layer1 node init: pack (s1,x), d1, zero agg1 ----------------
__global__ void k_node1_init(const float* __restrict__ x) {
    int v = blockIdx.x * blockDim.x + threadIdx.x;
    if (v >= N_NODES) return;
    float x0 = x[v * 3 + 0], x1 = x[v * 3 + 1], x2 = x[v * 3 + 2];
    float s = x0 * g_wa[0] + x1 * g_wa[1] + x2 * g_wa[2];
    float d = x0 * g_wa[3] + x1 * g_wa[4] + x2 * g_wa[5];
    g_x4[v] = make_float4(s, x0, x1, x2);
    g_d1[v] = d;
    g_agg1[v] = make_float4(0.f, 0.f, 0.f, 0.f);
}

// ---------------- layer1 edge pass: exp(logit) + v4 scatter --------------------
__global__ void __launch_bounds__(256) k_edgeB1(const int* __restrict__ ei) {
    int i = blockIdx.x * blockDim.x + threadIdx.x;
    if (i >= N_EDGES) return;
    int s = ei[i], d = ei[N_EDGES + i];
    float4 f = g_x4[s];
    float w = __expf(lrelu(f.x + g_d1[d]));
    red_add_v4((float*)&g_agg1[d], w, w * f.y, w * f.z, w * f.w);
}

// ------- layer1 finalize: self-loop, normalize, project W1, prep layer2 --------
__global__ void k_node1_fin(const float* __restrict__ W1,
                            const float* __restrict__ b1) {
    int v = blockIdx.x * blockDim.x + threadIdx.x;
    if (v >= N_NODES) return;
    float4 f = g_x4[v];
    float w = __expf(lrelu(f.x + g_d1[v]));       // self-loop weight
    float4 a = g_agg1[v];
    float inv = 1.f / (a.x + w);
    float t0 = (a.y + w * f.y) * inv;
    float t1 = (a.z + w * f.z) * inv;
    float t2 = (a.w + w * f.w) * inv;

    float y[8];
    float s2 = 0.f, d2 = 0.f;
    #pragma unroll
    for (int k = 0; k < 8; k++) {
        float t = t0 * W1[k] + t1 * W1[8 + k] + t2 * W1[16 + k] + b1[k];
        t = t > 0.f ? t : 0.f;                    // relu
        y[k] = t;
        s2 += t * g_wa[6 + k];
        d2 += t * g_wa[14 + k];
    }
    float4* hv = (float4*)(g_h + v * 12);
    hv[0] = make_float4(s2, y[0], y[1], y[2]);
    hv[1] = make_float4(y[3], y[4], y[5], y[6]);
    hv[2] = make_float4(y[7], d2, 0.f, 0.f);
    float4* ag = (float4*)(g_agg2 + v * 12);
    ag[0] = make_float4(0.f, 0.f, 0.f, 0.f);
    ag[1] = make_float4(0.f, 0.f, 0.f, 0.f);
    ag[2] = make_float4(0.f, 0.f, 0.f, 0.f);
}

// ---------------- layer2 edge pass: exp(logit) + 2x v4 + scalar scatter --------
__global__ void __launch_bounds__(256) k_edgeB2(const int* __restrict__ ei) {
    int i = blockIdx.x * blockDim.x + threadIdx.x;
    if (i >= N_EDGES) return;
    int s = ei[i], d = ei[N_EDGES + i];
    const float4* hp = (const float4*)(g_h + s * 12);
    float4 A = hp[0];                       // s2, h0, h1, h2
    float4 B = hp[1];                       // h3..h6
    float  h7 = g_h[s * 12 + 8];
    float  d2 = g_h[d * 12 + 9];
    float w = __expf(lrelu(A.x + d2));
    float* ag = g_agg2 + d * 12;
    atomicAdd(ag, w);
    red_add_v4(ag + 4, w * A.y, w * A.z, w * A.w, w * B.x);
    red_add_v4(ag + 8, w * B.y, w * B.z, w * B.w, w * h7);
}

// -------- layer2 finalize + W2 projection + ReLU + FC + graph pooling ----------
__global__ void k_node2_fin(const int* __restrict__ batch,
                            const float* __restrict__ W2,
                            const float* __restrict__ b2,
                            const float* __restrict__ fcw,
                            const float* __restrict__ fcb,
                            float* __restrict__ out) {
    __shared__ float4 sW2[512];   // [k][f/4] : k*64 + f4
    __shared__ float4 sb2[64];
    __shared__ float4 sfw[64];
    __shared__ float  sg[N_GRAPHS];

    int tid = threadIdx.x;
    for (int j = tid; j < 512; j += blockDim.x)
        sW2[j] = ((const float4*)W2)[j];
    for (int j = tid; j < 64; j += blockDim.x) {
        sb2[j] = ((const float4*)b2)[j];
        sfw[j] = ((const float4*)fcw)[j];
    }
    if (tid < N_GRAPHS) sg[tid] = 0.f;
    __syncthreads();

    int v = blockIdx.x * blockDim.x + tid;
    if (v < N_NODES) {
        const float4* hp = (const float4*)(g_h + v * 12);
        float4 A = hp[0];
        float4 B = hp[1];
        float4 C = hp[2];                         // h7, d2, -, -
        float w = __expf(lrelu(A.x + C.y));       // self-loop weight
        const float* ag = g_agg2 + v * 12;
        float inv = 1.f / (ag[0] + w);
        float t[8];
        t[0] = (ag[4]  + w * A.y) * inv;
        t[1] = (ag[5]  + w * A.z) * inv;
        t[2] = (ag[6]  + w * A.w) * inv;
        t[3] = (ag[7]  + w * B.x) * inv;
        t[4] = (ag[8]  + w * B.y) * inv;
        t[5] = (ag[9]  + w * B.z) * inv;
        t[6] = (ag[10] + w * B.w) * inv;
        t[7] = (ag[11] + w * C.x) * inv;

        float acc = 0.f;
        #pragma unroll 4
        for (int f4 = 0; f4 < 64; f4++) {
            float4 y = sb2[f4];
            #pragma unroll
            for (int k = 0; k < 8; k++) {
                float4 wv = sW2[k * 64 + f4];
                y.x += t[k] * wv.x;
                y.y += t[k] * wv.y;
                y.z += t[k] * wv.z;
                y.w += t[k] * wv.w;
            }
            y.x = y.x > 0.f ? y.x : 0.f;
            y.y = y.y > 0.f ? y.y : 0.f;
            y.z = y.z > 0.f ? y.z : 0.f;
            y.w = y.w > 0.f ? y.w : 0.f;
            float4 fw = sfw[f4];
            acc += y.x * fw.x + y.y * fw.y + y.z * fw.z + y.w * fw.w;
        }
        acc += fcb[0];
        atomicAdd(&sg[batch[v]], acc);
    }
    __syncthreads();
    if (tid < N_GRAPHS) atomicAdd(&out[tid], sg[tid]);
}

// --------------------------------- launch --------------------------------------
extern "C" void kernel_launch(void* const* d_in, const int* in_sizes, int n_in,
                              void* d_out, int out_size) {
    const float* x     = (const float*)d_in[0];
    const int*   ei    = (const int*)d_in[1];     // int64 delivered as int32
    // d_in[2] = edge_attr (unused)
    const int*   batch = (const int*)d_in[3];
    const float* W1    = (const float*)d_in[4];
    const float* as1   = (const float*)d_in[5];
    const float* ad1   = (const float*)d_in[6];
    const float* b1    = (const float*)d_in[7];
    const float* W2    = (const float*)d_in[8];
    const float* as2   = (const float*)d_in[9];
    const float* ad2   = (const float*)d_in[10];
    const float* b2    = (const float*)d_in[11];
    const float* fcw   = (const float*)d_in[12];
    const float* fcb   = (const float*)d_in[13];
    float*       out   = (float*)d_out;

    const int EB = (N_EDGES + 255) / 256;   // 3125
    const int NB = (N_NODES + 255) / 256;   // 196

    k_prep<<<1, 320>>>(W1, as1, ad1, W2, as2, ad2, out);
    k_node1_init<<<NB, 256>>>(x);
    k_edgeB1<<<EB, 256>>>(ei);
    k_node1_fin<<<NB, 256>>>(W1, b1);
    k_edgeB2<<<EB, 256>>>(ei);
    k_node2_fin<<<NB, 256>>>(batch, W2, b2, fcw, fcb, out);
}